// round 17
// baseline (speedup 1.0000x reference)
#include <cuda_runtime.h>
#include <cuda_bf16.h>
#include <math.h>
#include <stdint.h>

// Problem constants (fixed by the reference)
#define N_NODES  100000
#define N_EDGES  300000
#define D_IN     256
#define HID      1024
#define N_CLS    64

// ---------------------------------------------------------------------------
// Scratch (device globals: allocation-free)
// ---------------------------------------------------------------------------
__device__ __nv_bfloat16 g_Ah[(size_t)N_NODES * HID];       // act bf16 ping
__device__ __nv_bfloat16 g_Ch[(size_t)N_NODES * HID];       // act bf16 pong
__device__ __nv_bfloat16 g_Wh[(size_t)HID * HID];           // weight bf16 [K][N]
__device__ __nv_bfloat16 g_Wc[(size_t)HID * 128];           // composed cls W [K][128]
__device__ float g_bfcPad[128];                             // composed cls bias
__device__ int   g_edges[2 * N_EDGES];
__device__ int   g_idx64;
// CSR scratch
__device__ int g_deg[N_NODES];
__device__ int g_incl[N_NODES];
__device__ int g_ptr[N_NODES];
__device__ int g_cursor[N_NODES];
__device__ int g_blockSums[128];
__device__ int g_csr_idx[N_EDGES];

// ---------------------------------------------------------------------------
// PTX helpers (all sm_80-era: valid under compute_103, no 'a' features)
// ---------------------------------------------------------------------------
__device__ __forceinline__ uint32_t s2u(const void* p) {
    uint32_t a;
    asm("{ .reg .u64 t; cvta.to.shared.u64 t, %1; cvt.u32.u64 %0, t; }"
        : "=r"(a) : "l"(p));
    return a;
}

__device__ __forceinline__ void cp_async16(uint32_t s, const void* g, unsigned sz) {
    asm volatile("cp.async.cg.shared.global [%0], [%1], 16, %2;"
                 :: "r"(s), "l"(g), "r"(sz));
}

__device__ __forceinline__ void ldsm4(uint32_t* r, uint32_t addr) {
    asm volatile("ldmatrix.sync.aligned.m8n8.x4.shared.b16 {%0,%1,%2,%3}, [%4];"
                 : "=r"(r[0]), "=r"(r[1]), "=r"(r[2]), "=r"(r[3]) : "r"(addr));
}

__device__ __forceinline__ void ldsm4t(uint32_t* r, uint32_t addr) {
    asm volatile("ldmatrix.sync.aligned.m8n8.x4.trans.shared.b16 {%0,%1,%2,%3}, [%4];"
                 : "=r"(r[0]), "=r"(r[1]), "=r"(r[2]), "=r"(r[3]) : "r"(addr));
}

__device__ __forceinline__ void mma_bf16(float* d, const uint32_t* a,
                                         const uint32_t* b) {
    asm volatile(
        "mma.sync.aligned.m16n8k16.row.col.f32.bf16.bf16.f32 "
        "{%0,%1,%2,%3},{%4,%5,%6,%7},{%8,%9},{%0,%1,%2,%3};"
        : "+f"(d[0]), "+f"(d[1]), "+f"(d[2]), "+f"(d[3])
        : "r"(a[0]), "r"(a[1]), "r"(a[2]), "r"(a[3]), "r"(b[0]), "r"(b[1]));
}

// ---------------------------------------------------------------------------
// Edge-index dtype detection + normalization (+ fused CSR zero)
// ---------------------------------------------------------------------------
__global__ void detect_idx_kernel(const unsigned int* __restrict__ ei) {
    unsigned v = ei[2 * threadIdx.x + 1];
    int any = __syncthreads_or(v != 0u);
    if (threadIdx.x == 0) g_idx64 = any ? 0 : 1;
}

__global__ void convert_idx_kernel(const unsigned int* __restrict__ ei) {
    int i = blockIdx.x * blockDim.x + threadIdx.x;
    if (i < 2 * N_EDGES) g_edges[i] = g_idx64 ? (int)ei[2 * i] : (int)ei[i];
    if (i < N_NODES) { g_deg[i] = 0; g_cursor[i] = 0; }
}

// ---------------------------------------------------------------------------
// CSR build: degree count -> block scan -> ptr -> atomic-slot fill
// ---------------------------------------------------------------------------
__global__ void count_deg_kernel() {
    int e = blockIdx.x * blockDim.x + threadIdx.x;
    if (e < N_EDGES) atomicAdd(&g_deg[g_edges[N_EDGES + e]], 1);
}

__global__ void scan_block_kernel() {
    __shared__ int s[1024];
    int g = blockIdx.x * 1024 + threadIdx.x;
    int v = (g < N_NODES) ? g_deg[g] : 0;
    s[threadIdx.x] = v;
    __syncthreads();
#pragma unroll
    for (int off = 1; off < 1024; off <<= 1) {
        int t = (threadIdx.x >= off) ? s[threadIdx.x - off] : 0;
        __syncthreads();
        s[threadIdx.x] += t;
        __syncthreads();
    }
    if (g < N_NODES) g_incl[g] = s[threadIdx.x];
    if (threadIdx.x == 1023) g_blockSums[blockIdx.x] = s[1023];
}

__global__ void scan_sums_kernel(int nb) {
    if (threadIdx.x == 0) {
        int run = 0;
        for (int i = 0; i < nb; i++) { int t = g_blockSums[i]; g_blockSums[i] = run; run += t; }
    }
}

__global__ void finalize_ptr_kernel() {
    int g = blockIdx.x * blockDim.x + threadIdx.x;
    if (g < N_NODES) g_ptr[g] = g_incl[g] - g_deg[g] + g_blockSums[g >> 10];
}

__global__ void fill_csr_kernel() {
    int e = blockIdx.x * blockDim.x + threadIdx.x;
    if (e < N_EDGES) {
        int s = g_edges[e];
        int d = g_edges[N_EDGES + e];
        int slot = atomicAdd(&g_cursor[d], 1);
        g_csr_idx[g_ptr[d] + slot] = s;
    }
}

// ---------------------------------------------------------------------------
// Gather aggregation, layer 1: O[i] = bf16(x[i] + sum_j x[j]), D=256 fp32 in
// ---------------------------------------------------------------------------
__global__ void __launch_bounds__(128)
gather_x_kernel(const float2* __restrict__ X, __nv_bfloat162* __restrict__ O) {
    __shared__ int sidx[64];
    int node = blockIdx.x;
    int t = threadIdx.x;
    float2 a = X[(size_t)node * 128 + t];
    int st = g_ptr[node];
    int de = g_deg[node];
    for (int base = 0; base < de; base += 64) {
        int cnt = min(64, de - base);
        if (t < cnt) sidx[t] = g_csr_idx[st + base + t];
        __syncthreads();
        int q = 0;
        if (cnt & 1) {
            float2 v = X[(size_t)sidx[0] * 128 + t];
            a.x += v.x; a.y += v.y;
            q = 1;
        }
        for (; q < cnt; q += 2) {
            float2 v0 = X[(size_t)sidx[q] * 128 + t];
            float2 v1 = X[(size_t)sidx[q + 1] * 128 + t];
            a.x += v0.x; a.y += v0.y;
            a.x += v1.x; a.y += v1.y;
        }
        __syncthreads();
    }
    O[(size_t)node * 128 + t] = __nv_bfloat162(__float2bfloat16(a.x),
                                               __float2bfloat16(a.y));
}

// ---------------------------------------------------------------------------
// Gather aggregation, layer 2: O[i] = bf16(H[i] + sum_j H[j]), D=1024 bf16 in
// ---------------------------------------------------------------------------
__device__ __forceinline__ void acc_u4(float* acc, uint4 v) {
    float2 p0 = __bfloat1622float2(*(__nv_bfloat162*)&v.x);
    float2 p1 = __bfloat1622float2(*(__nv_bfloat162*)&v.y);
    float2 p2 = __bfloat1622float2(*(__nv_bfloat162*)&v.z);
    float2 p3 = __bfloat1622float2(*(__nv_bfloat162*)&v.w);
    acc[0] += p0.x; acc[1] += p0.y; acc[2] += p1.x; acc[3] += p1.y;
    acc[4] += p2.x; acc[5] += p2.y; acc[6] += p3.x; acc[7] += p3.y;
}

__global__ void __launch_bounds__(128)
gather_h_kernel(const uint4* __restrict__ H, uint4* __restrict__ O) {
    __shared__ int sidx[64];
    int node = blockIdx.x;
    int t = threadIdx.x;
    float acc[8];
    {
        uint4 sv = H[(size_t)node * 128 + t];
        float2 p0 = __bfloat1622float2(*(__nv_bfloat162*)&sv.x);
        float2 p1 = __bfloat1622float2(*(__nv_bfloat162*)&sv.y);
        float2 p2 = __bfloat1622float2(*(__nv_bfloat162*)&sv.z);
        float2 p3 = __bfloat1622float2(*(__nv_bfloat162*)&sv.w);
        acc[0] = p0.x; acc[1] = p0.y; acc[2] = p1.x; acc[3] = p1.y;
        acc[4] = p2.x; acc[5] = p2.y; acc[6] = p3.x; acc[7] = p3.y;
    }
    int st = g_ptr[node];
    int de = g_deg[node];
    for (int base = 0; base < de; base += 64) {
        int cnt = min(64, de - base);
        if (t < cnt) sidx[t] = g_csr_idx[st + base + t];
        __syncthreads();
        int q = 0;
        if (cnt & 1) {
            uint4 v = H[(size_t)sidx[0] * 128 + t];
            acc_u4(acc, v);
            q = 1;
        }
        for (; q < cnt; q += 2) {
            uint4 v0 = H[(size_t)sidx[q] * 128 + t];
            uint4 v1 = H[(size_t)sidx[q + 1] * 128 + t];
            acc_u4(acc, v0);
            acc_u4(acc, v1);
        }
        __syncthreads();
    }
    uint4 o;
    *(__nv_bfloat162*)&o.x = __nv_bfloat162(__float2bfloat16(acc[0]), __float2bfloat16(acc[1]));
    *(__nv_bfloat162*)&o.y = __nv_bfloat162(__float2bfloat16(acc[2]), __float2bfloat16(acc[3]));
    *(__nv_bfloat162*)&o.z = __nv_bfloat162(__float2bfloat16(acc[4]), __float2bfloat16(acc[5]));
    *(__nv_bfloat162*)&o.w = __nv_bfloat162(__float2bfloat16(acc[6]), __float2bfloat16(acc[7]));
    O[(size_t)node * 128 + t] = o;
}

// ---------------------------------------------------------------------------
// Coalesced fp32 -> bf16 weight convert (natural [K][N] layout, no transpose)
// ---------------------------------------------------------------------------
__global__ void convert_w_kernel(const float4* __restrict__ W,
                                 __nv_bfloat162* __restrict__ O, int n4) {
    int i = blockIdx.x * 256 + threadIdx.x;
    if (i < n4) {
        float4 v = W[i];
        O[2 * i]     = __nv_bfloat162(__float2bfloat16(v.x), __float2bfloat16(v.y));
        O[2 * i + 1] = __nv_bfloat162(__float2bfloat16(v.z), __float2bfloat16(v.w));
    }
}

// ---------------------------------------------------------------------------
// Classifier composition: Wc[k][j] = sum_n W2b[k][n] * Wfc[n][j], j<64;
// cols 64..127 zero-padded. Natural [K][128] layout.
// ---------------------------------------------------------------------------
__global__ void __launch_bounds__(256)
compose_cls_kernel(const float* __restrict__ W2b, const float* __restrict__ Wfc,
                   __nv_bfloat16* __restrict__ T) {
    int j = threadIdx.x;                       // 0..127
    int k = blockIdx.x * 2 + threadIdx.y;      // 0..1023
    float acc = 0.0f;
    if (j < N_CLS) {
        const float* wrow = W2b + (size_t)k * HID;
#pragma unroll 4
        for (int n = 0; n < HID; ++n)
            acc = fmaf(wrow[n], Wfc[(size_t)n * N_CLS + j], acc);
    }
    T[(size_t)k * 128 + j] = __float2bfloat16(acc);
}

__global__ void compose_bias_kernel(const float* __restrict__ b2b,
                                    const float* __restrict__ Wfc,
                                    const float* __restrict__ bfc) {
    int j = threadIdx.x;                       // 0..127
    float acc = 0.0f;
    if (j < N_CLS) {
#pragma unroll 4
        for (int n = 0; n < HID; ++n)
            acc = fmaf(b2b[n], Wfc[(size_t)n * N_CLS + j], acc);
        acc += bfc[j];
    }
    g_bfcPad[j] = acc;
}

// ---------------------------------------------------------------------------
// Pure-bf16 mma.sync GEMM:  C[M, ncols] = act(A[M,K] @ W[K,ncols] + bias)
// A bf16 [M,K] (k-major); W bf16 [K,Nw] NATURAL layout, transposed at
// fragment load via ldmatrix.trans. BM=128, BN=128, BK=64, 256 threads.
// 3-stage cp.async pipeline (32KB/stage -> 2 CTAs/SM).
// OUT: 0 = fp32 to C (stride ostride, col guard); 2 = bf16 hi;
//      3 = fused bias + log_softmax over cols 0..63 -> C [M,64].
// ---------------------------------------------------------------------------
static constexpr uint32_t STAGE_SZ = 32768u;
static constexpr uint32_t OFF_BH   = 16384u;

template <int K>
__device__ __forceinline__ void load_stage(uint32_t tbase, int stage,
    const __nv_bfloat16* __restrict__ Ah, const __nv_bfloat16* __restrict__ Bh,
    int chunk, int rowBase, int colBase, int M, int Nw) {
    const int tid = threadIdx.x;
    const uint32_t sBase = tbase + (uint32_t)stage * STAGE_SZ;
    const long kOff = (long)chunk * 64;
#pragma unroll
    for (int i = 0; i < 4; ++i) {
        int t = i * 256 + tid;
        // A: 128 rows x 8 chunks of 16B (k-major, 128B rows, SW swizzle)
        int r = t >> 3;
        int cc = t & 7;
        uint32_t swA = (uint32_t)(r * 128 + ((cc ^ (r & 7)) << 4));
        int gr = rowBase + r;
        unsigned sz = (gr < M) ? 16u : 0u;
        int ga = gr < M ? gr : (M - 1);
        cp_async16(sBase + swA,
                   (const char*)Ah + ((size_t)ga * K + kOff + cc * 8) * 2, sz);
        // B: 64 k-rows x 16 chunks of 16B (n-major 256B rows, swizzled)
        int rb = t >> 4;
        int cb = t & 15;
        uint32_t swB = (uint32_t)(rb * 256 + ((cb ^ (rb & 7)) << 4));
        cp_async16(sBase + OFF_BH + swB,
                   (const char*)Bh + ((size_t)(kOff + rb) * Nw + colBase + cb * 8) * 2,
                   16u);
    }
}

struct Frags {
    uint32_t ah[4][4];
    uint32_t bh[2][4];
};

__device__ __forceinline__ void load_frags(uint32_t st, int k,
                                           const int* arow, int a_ck,
                                           int bk, const int* bchunk, Frags& f) {
#pragma unroll
    for (int fm = 0; fm < 4; ++fm) {
        int row = arow[fm];
        int ck = k * 2 + a_ck;
        uint32_t off = (uint32_t)(row * 128 + ((ck ^ (row & 7)) << 4));
        ldsm4(f.ah[fm], st + off);
    }
#pragma unroll
    for (int f2 = 0; f2 < 2; ++f2) {
        int krow = k * 16 + bk;
        uint32_t off = (uint32_t)(krow * 256 + ((bchunk[f2] ^ (krow & 7)) << 4));
        ldsm4t(f.bh[f2], st + OFF_BH + off);
    }
}

__device__ __forceinline__ void mma_frags(const Frags& f, float acc[4][4][4]) {
#pragma unroll
    for (int fm = 0; fm < 4; ++fm)
#pragma unroll
        for (int fn = 0; fn < 4; ++fn)
            mma_bf16(acc[fm][fn], f.ah[fm], &f.bh[fn >> 1][(fn & 1) * 2]);
}

template <int K, bool RELU, int OUT>
__global__ void __launch_bounds__(256, 2)
gemm_bf16_mma_kernel(const __nv_bfloat16* __restrict__ Ah,
                     const __nv_bfloat16* __restrict__ Bh,
                     const float* __restrict__ bias,
                     float* __restrict__ C,
                     __nv_bfloat162* __restrict__ Oh,
                     int M, int ostride, int ncols, int Nw) {
    constexpr int NC = K / 64;
    extern __shared__ char smem[];
    const uint32_t tile_base = (s2u(smem) + 1023u) & ~1023u;

    const int tid = threadIdx.x;
    const int wid = tid >> 5;
    const int lane = tid & 31;
    const int wm = wid >> 2;          // 0..1
    const int wn = wid & 3;           // 0..3
    const int rowBase = blockIdx.y * 128;
    const int colBase = blockIdx.x * 128;

    const int midx = lane >> 3;
    const int l7 = lane & 7;
    const int a_ck = (midx >> 1);
    int arow[4];
#pragma unroll
    for (int fm = 0; fm < 4; ++fm)
        arow[fm] = wm * 64 + fm * 16 + ((midx & 1) << 3) + l7;
    // B (trans path): k-row offset within 16-k step + n-chunk per 16-n group
    const int bk = ((midx & 1) << 3) + l7;
    int bchunk[2];
#pragma unroll
    for (int f2 = 0; f2 < 2; ++f2)
        bchunk[f2] = wn * 4 + f2 * 2 + (midx >> 1);

    float acc[4][4][4];
#pragma unroll
    for (int i = 0; i < 4; i++)
#pragma unroll
        for (int j = 0; j < 4; j++)
#pragma unroll
            for (int q = 0; q < 4; q++) acc[i][j][q] = 0.0f;

    // Prologue: prefetch chunks 0, 1
    load_stage<K>(tile_base, 0, Ah, Bh, 0, rowBase, colBase, M, Nw);
    asm volatile("cp.async.commit_group;" ::: "memory");
    load_stage<K>(tile_base, 1, Ah, Bh, 1, rowBase, colBase, M, Nw);
    asm volatile("cp.async.commit_group;" ::: "memory");

    Frags fr;
    for (int c = 0; c < NC; ++c) {
        if (c + 1 < NC) asm volatile("cp.async.wait_group 1;" ::: "memory");
        else            asm volatile("cp.async.wait_group 0;" ::: "memory");
        __syncthreads();
        const uint32_t st = tile_base + (uint32_t)(c % 3) * STAGE_SZ;
        if (c + 2 < NC) {
            load_stage<K>(tile_base, (c + 2) % 3, Ah, Bh, c + 2,
                          rowBase, colBase, M, Nw);
            asm volatile("cp.async.commit_group;" ::: "memory");
        }
#pragma unroll
        for (int k = 0; k < 4; ++k) {
            load_frags(st, k, arow, a_ck, bk, bchunk, fr);
            mma_frags(fr, acc);
        }
    }

    // Epilogue
    float* slog = (float*)smem;                 // OUT==3: logits staging (128x65)
    if (OUT == 3) __syncthreads();              // stages dead; safe to reuse
    const int rowb = rowBase + wm * 64 + (lane >> 2);
    const int colb = colBase + wn * 32;
#pragma unroll
    for (int fm = 0; fm < 4; ++fm) {
        int r0 = rowb + fm * 16;
        int r1 = r0 + 8;
#pragma unroll
        for (int fn = 0; fn < 4; ++fn) {
            int col = colb + fn * 8 + (lane & 3) * 2;
            float2 bp = *reinterpret_cast<const float2*>(&bias[col]);
            float v0 = acc[fm][fn][0] + bp.x;
            float v1 = acc[fm][fn][1] + bp.y;
            float v2 = acc[fm][fn][2] + bp.x;
            float v3 = acc[fm][fn][3] + bp.y;
            if (RELU) {
                v0 = fmaxf(v0, 0.f); v1 = fmaxf(v1, 0.f);
                v2 = fmaxf(v2, 0.f); v3 = fmaxf(v3, 0.f);
            }
            if (OUT == 3) {
                if (wn < 2) {                   // cols 0..63 only
                    int rl = wm * 64 + fm * 16 + (lane >> 2);
                    slog[rl * 65 + col]       = v0;
                    slog[rl * 65 + col + 1]   = v1;
                    slog[(rl + 8) * 65 + col]     = v2;
                    slog[(rl + 8) * 65 + col + 1] = v3;
                }
            } else if (OUT == 0) {
                if (col < ncols) {
                    if (r0 < M)
                        *reinterpret_cast<float2*>(&C[(size_t)r0 * ostride + col]) =
                            make_float2(v0, v1);
                    if (r1 < M)
                        *reinterpret_cast<float2*>(&C[(size_t)r1 * ostride + col]) =
                            make_float2(v2, v3);
                }
            } else {
                if (r0 < M) {
                    size_t h = ((size_t)r0 * ostride + col) >> 1;
                    Oh[h] = __nv_bfloat162(__float2bfloat16(v0),
                                           __float2bfloat16(v1));
                }
                if (r1 < M) {
                    size_t h = ((size_t)r1 * ostride + col) >> 1;
                    Oh[h] = __nv_bfloat162(__float2bfloat16(v2),
                                           __float2bfloat16(v3));
                }
            }
        }
    }
    if (OUT == 3) {
        __syncthreads();
        if (tid < 128) {                        // one thread per row: lse
            float m = -1e30f;
#pragma unroll 4
            for (int j = 0; j < 64; ++j) m = fmaxf(m, slog[tid * 65 + j]);
            float s = 0.0f;
#pragma unroll 4
            for (int j = 0; j < 64; ++j) s += expf(slog[tid * 65 + j] - m);
            slog[tid * 65 + 64] = m + logf(s);
        }
        __syncthreads();
        for (int e = tid; e < 128 * 64; e += 256) {
            int rr = e >> 6, cc2 = e & 63;
            int gr2 = rowBase + rr;
            if (gr2 < M)
                C[(size_t)gr2 * 64 + cc2] = slog[rr * 65 + cc2] - slog[rr * 65 + 64];
        }
    }
}

// ---------------------------------------------------------------------------
// Launch
// ---------------------------------------------------------------------------
extern "C" void kernel_launch(void* const* d_in, const int* in_sizes, int n_in,
                              void* d_out, int out_size) {
    const float*        x   = (const float*)d_in[0];
    const unsigned int* ei  = (const unsigned int*)d_in[1];
    const float* W1a = (const float*)d_in[2];
    const float* b1a = (const float*)d_in[3];
    const float* W1b = (const float*)d_in[4];
    const float* b1b = (const float*)d_in[5];
    const float* W2a = (const float*)d_in[6];
    const float* b2a = (const float*)d_in[7];
    const float* W2b = (const float*)d_in[8];
    const float* b2b = (const float*)d_in[9];
    const float* Wfc = (const float*)d_in[10];
    const float* bfc = (const float*)d_in[11];
    float* out = (float*)d_out;

    float *bfcPad;
    __nv_bfloat16 *Ah, *Ch, *Wh, *Wc;
    cudaGetSymbolAddress((void**)&Ah, g_Ah);
    cudaGetSymbolAddress((void**)&Ch, g_Ch);
    cudaGetSymbolAddress((void**)&Wh, g_Wh);
    cudaGetSymbolAddress((void**)&Wc, g_Wc);
    cudaGetSymbolAddress((void**)&bfcPad, g_bfcPad);

    // 3 x 32KB stages + align slack -> 2 CTAs/SM
    const int GEMM_SMEM = 3 * 32768 + 1024;   // 99328 B
    cudaFuncSetAttribute(gemm_bf16_mma_kernel<256, true, 2>,
                         cudaFuncAttributeMaxDynamicSharedMemorySize, GEMM_SMEM);
    cudaFuncSetAttribute(gemm_bf16_mma_kernel<1024, true, 2>,
                         cudaFuncAttributeMaxDynamicSharedMemorySize, GEMM_SMEM);
    cudaFuncSetAttribute(gemm_bf16_mma_kernel<1024, false, 3>,
                         cudaFuncAttributeMaxDynamicSharedMemorySize, GEMM_SMEM);

    // ---- Edge normalization + CSR build ----
    detect_idx_kernel<<<1, 256>>>(ei);
    convert_idx_kernel<<<(2 * N_EDGES + 255) / 256, 256>>>(ei);
    count_deg_kernel<<<(N_EDGES + 255) / 256, 256>>>();
    const int NB = (N_NODES + 1023) / 1024;   // 98
    scan_block_kernel<<<NB, 1024>>>();
    scan_sums_kernel<<<1, 32>>>(NB);
    finalize_ptr_kernel<<<(N_NODES + 255) / 256, 256>>>();
    fill_csr_kernel<<<(N_EDGES + 255) / 256, 256>>>();

    // ---- Classifier composition ----
    compose_cls_kernel<<<HID / 2, dim3(128, 2)>>>(W2b, Wfc, Wc);
    compose_bias_kernel<<<1, 128>>>(b2b, Wfc, bfc);

    dim3 gridGemm(HID / 128, (N_NODES + 127) / 128);   // (8, 782)
    dim3 gridFC(1, (N_NODES + 127) / 128);

    // ---- Layer 1: Ah = bf16(x + gather(x)) ----
    gather_x_kernel<<<N_NODES, 128>>>((const float2*)x, (__nv_bfloat162*)Ah);
    // GEMM1a: Ch = bf16(relu(Ah @ W1a + b1a))
    convert_w_kernel<<<(D_IN * HID / 4 + 255) / 256, 256>>>(
        (const float4*)W1a, (__nv_bfloat162*)Wh, D_IN * HID / 4);
    gemm_bf16_mma_kernel<256, true, 2><<<gridGemm, 256, GEMM_SMEM>>>(
        Ah, Wh, b1a, nullptr, (__nv_bfloat162*)Ch, N_NODES, HID, HID, HID);
    // GEMM1b: Ah = bf16(relu(Ch @ W1b + b1b)) = h1
    convert_w_kernel<<<(HID * HID / 4 + 255) / 256, 256>>>(
        (const float4*)W1b, (__nv_bfloat162*)Wh, HID * HID / 4);
    gemm_bf16_mma_kernel<1024, true, 2><<<gridGemm, 256, GEMM_SMEM>>>(
        Ch, Wh, b1b, nullptr, (__nv_bfloat162*)Ah, N_NODES, HID, HID, HID);

    // ---- Layer 2: Ch = bf16(h1 + gather(h1)) ----
    gather_h_kernel<<<N_NODES, 128>>>((const uint4*)Ah, (uint4*)Ch);
    // GEMM2a: Ah = bf16(relu(Ch @ W2a + b2a)) = h_act
    convert_w_kernel<<<(HID * HID / 4 + 255) / 256, 256>>>(
        (const float4*)W2a, (__nv_bfloat162*)Wh, HID * HID / 4);
    gemm_bf16_mma_kernel<1024, true, 2><<<gridGemm, 256, GEMM_SMEM>>>(
        Ch, Wh, b2a, nullptr, (__nv_bfloat162*)Ah, N_NODES, HID, HID, HID);

    // ---- Fused classifier + log_softmax: out = lsm(h_act @ Wc + bc) ----
    gemm_bf16_mma_kernel<1024, false, 3><<<gridFC, 256, GEMM_SMEM>>>(
        Ah, Wc, bfcPad, out, nullptr, N_NODES, N_CLS, N_CLS, 128);
}